// round 1
// baseline (speedup 1.0000x reference)
#include <cuda_runtime.h>
#include <cuda_bf16.h>
#include <cstdint>

// Problem dims (fixed by the dataset)
#define Bz 32
#define Tz 1000
#define Hz 512
#define Vz 2048
#define Lz 100
#define BTz (Bz*Tz)
#define Sz (2*Lz+1)           // 201
#define NLAB 101              // blank + L labels
#define NEGINF (-1e10f)

// ---------------- device scratch (static: no allocation) ----------------
__device__ __nv_bfloat16 g_Abf[BTz*Hz];        // eouts in bf16      (~32.8 MB)
__device__ __nv_bfloat16 g_Wbf[Vz*Hz];         // W in bf16          (~2.1 MB)
__device__ __nv_bfloat16 g_Wlab[Bz*128*Hz];    // gathered label W rows (padded to 128)
__device__ float         g_blab[Bz*128];       // gathered label biases
__device__ float         g_lse[BTz];           // logsumexp per (b,t)
__device__ float         g_lab[(size_t)BTz*NLAB]; // label log-probs (logit+bias-lse)
__device__ float         g_lossb[Bz];

// ---------------- helpers ----------------
__device__ __forceinline__ void mma16816(float* c, uint32_t a0, uint32_t a1,
                                         uint32_t a2, uint32_t a3,
                                         uint32_t b0, uint32_t b1) {
    asm volatile(
        "mma.sync.aligned.m16n8k16.row.col.f32.bf16.bf16.f32 "
        "{%0,%1,%2,%3}, {%4,%5,%6,%7}, {%8,%9}, {%0,%1,%2,%3};\n"
        : "+f"(c[0]), "+f"(c[1]), "+f"(c[2]), "+f"(c[3])
        : "r"(a0), "r"(a1), "r"(a2), "r"(a3), "r"(b0), "r"(b1));
}

#define A_STR 520   // bf16 elems per A smem row (512 + 8 pad -> conflict-free LDS)
#define W_STR 72    // bf16 elems per W smem row (64 + 8 pad)
#define SMEM_BYTES ((128*A_STR + 2*128*W_STR) * 2)

// ---------------- kernel 1: fp32 -> bf16 conversion ----------------
__global__ void k_convert(const float* __restrict__ e, const float* __restrict__ Wm) {
    const int nA2 = (BTz*Hz)/2, nW2 = (Vz*Hz)/2;
    __nv_bfloat162* A2 = reinterpret_cast<__nv_bfloat162*>(g_Abf);
    __nv_bfloat162* W2 = reinterpret_cast<__nv_bfloat162*>(g_Wbf);
    const float2* e2 = reinterpret_cast<const float2*>(e);
    const float2* w2 = reinterpret_cast<const float2*>(Wm);
    for (int i = blockIdx.x*blockDim.x + threadIdx.x; i < nA2 + nW2;
         i += gridDim.x*blockDim.x) {
        if (i < nA2) { float2 v = e2[i]; A2[i] = __floats2bfloat162_rn(v.x, v.y); }
        else         { float2 v = w2[i-nA2]; W2[i-nA2] = __floats2bfloat162_rn(v.x, v.y); }
    }
}

// ---------------- kernel 2: gather label W rows + biases ----------------
__global__ void k_gather(const float* __restrict__ bias, const int* __restrict__ ys) {
    int idx = blockIdx.x;            // b*128 + j
    int b = idx >> 7, j = idx & 127;
    int v = (j == 0) ? 0 : ((j <= Lz) ? ys[b*Lz + j - 1] : -1);
    uint4* dst = reinterpret_cast<uint4*>(g_Wlab + (size_t)idx*Hz);
    if (v >= 0) {
        const uint4* src = reinterpret_cast<const uint4*>(g_Wbf + (size_t)v*Hz);
        dst[threadIdx.x] = src[threadIdx.x];     // 64 threads x 16B = 1KB row
    } else {
        dst[threadIdx.x] = make_uint4(0u,0u,0u,0u);
    }
    if (threadIdx.x == 0) g_blab[idx] = (v >= 0) ? bias[v] : 0.f;
}

// ---------------- kernel 3: GEMM + online logsumexp ----------------
// Block: 128 rows of (b,t), loops over all V in 128-col chunks. 8 warps,
// each warp owns 16 rows x 128 cols -> per-row LSE state stays in registers.
__global__ __launch_bounds__(256, 1) void k_lse(const float* __restrict__ bias) {
    extern __shared__ __nv_bfloat16 sm[];
    __nv_bfloat16* As = sm;                 // [128][A_STR]
    __nv_bfloat16* Ws = sm + 128*A_STR;     // [2][128][W_STR]
    const int tid = threadIdx.x;
    const int w = tid >> 5, lane = tid & 31, g = lane >> 2, tig = lane & 3;
    const int r0 = blockIdx.x * 128;
    const int rowA = w*16 + g;

    // Load A tile [128 x 512] fully (uint4 = 8 bf16; 64 per row)
    for (int e = tid; e < 128*64; e += 256) {
        int row = e >> 6, c = e & 63;
        *reinterpret_cast<uint4*>(As + row*A_STR + c*8) =
            *reinterpret_cast<const uint4*>(g_Abf + (size_t)(r0+row)*Hz + c*8);
    }

    float M0 = -3e38f, S0 = 0.f, M1 = -3e38f, S1 = 0.f;

    #pragma unroll 1
    for (int nc = 0; nc < Vz/128; nc++) {
        const int vbase = nc * 128;
        uint2 rg[8];
        // stage K-chunk 0 into buffer 0
        #pragma unroll
        for (int q = 0; q < 8; q++) {
            int e = tid + q*256; int row = e >> 4, c = e & 15;
            rg[q] = *reinterpret_cast<const uint2*>(g_Wbf + (size_t)(vbase+row)*Hz + c*4);
        }
        #pragma unroll
        for (int q = 0; q < 8; q++) {
            int e = tid + q*256; int row = e >> 4, c = e & 15;
            *reinterpret_cast<uint2*>(Ws + row*W_STR + c*4) = rg[q];
        }
        __syncthreads();

        float acc[16][4];
        #pragma unroll
        for (int i = 0; i < 16; i++) { acc[i][0]=0.f; acc[i][1]=0.f; acc[i][2]=0.f; acc[i][3]=0.f; }

        #pragma unroll 1
        for (int kc = 0; kc < 8; kc++) {
            if (kc < 7) {
                #pragma unroll
                for (int q = 0; q < 8; q++) {
                    int e = tid + q*256; int row = e >> 4, c = e & 15;
                    rg[q] = *reinterpret_cast<const uint2*>(
                        g_Wbf + (size_t)(vbase+row)*Hz + (kc+1)*64 + c*4);
                }
            }
            const __nv_bfloat16* Wb = Ws + (kc & 1) * (128*W_STR);
            #pragma unroll
            for (int ks = 0; ks < 4; ks++) {
                const int kk = kc*64 + ks*16;
                uint32_t a0 = *reinterpret_cast<const uint32_t*>(As + rowA*A_STR + kk + 2*tig);
                uint32_t a1 = *reinterpret_cast<const uint32_t*>(As + (rowA+8)*A_STR + kk + 2*tig);
                uint32_t a2 = *reinterpret_cast<const uint32_t*>(As + rowA*A_STR + kk + 8 + 2*tig);
                uint32_t a3 = *reinterpret_cast<const uint32_t*>(As + (rowA+8)*A_STR + kk + 8 + 2*tig);
                #pragma unroll
                for (int nt = 0; nt < 16; nt++) {
                    uint32_t b0 = *reinterpret_cast<const uint32_t*>(Wb + (nt*8+g)*W_STR + ks*16 + 2*tig);
                    uint32_t b1 = *reinterpret_cast<const uint32_t*>(Wb + (nt*8+g)*W_STR + ks*16 + 8 + 2*tig);
                    mma16816(acc[nt], a0, a1, a2, a3, b0, b1);
                }
            }
            __syncthreads();
            if (kc < 7) {
                __nv_bfloat16* Wd = Ws + ((kc+1) & 1) * (128*W_STR);
                #pragma unroll
                for (int q = 0; q < 8; q++) {
                    int e = tid + q*256; int row = e >> 4, c = e & 15;
                    *reinterpret_cast<uint2*>(Wd + row*W_STR + c*4) = rg[q];
                }
                __syncthreads();
            }
        }

        // Epilogue: add bias, per-row chunk (max,sumexp), quad reduce, running update
        float m0 = -3e38f, m1 = -3e38f;
        #pragma unroll
        for (int nt = 0; nt < 16; nt++) {
            int v = vbase + nt*8 + 2*tig;
            float bb0 = __ldg(&bias[v]), bb1 = __ldg(&bias[v+1]);
            acc[nt][0] += bb0; acc[nt][1] += bb1; acc[nt][2] += bb0; acc[nt][3] += bb1;
            m0 = fmaxf(m0, fmaxf(acc[nt][0], acc[nt][1]));
            m1 = fmaxf(m1, fmaxf(acc[nt][2], acc[nt][3]));
        }
        float s0 = 0.f, s1 = 0.f;
        #pragma unroll
        for (int nt = 0; nt < 16; nt++) {
            s0 += __expf(acc[nt][0]-m0) + __expf(acc[nt][1]-m0);
            s1 += __expf(acc[nt][2]-m1) + __expf(acc[nt][3]-m1);
        }
        #pragma unroll
        for (int off = 1; off <= 2; off <<= 1) {
            float mo = __shfl_xor_sync(0xffffffffu, m0, off);
            float so = __shfl_xor_sync(0xffffffffu, s0, off);
            float mn = fmaxf(m0, mo);
            s0 = s0*__expf(m0-mn) + so*__expf(mo-mn); m0 = mn;
            mo = __shfl_xor_sync(0xffffffffu, m1, off);
            so = __shfl_xor_sync(0xffffffffu, s1, off);
            mn = fmaxf(m1, mo);
            s1 = s1*__expf(m1-mn) + so*__expf(mo-mn); m1 = mn;
        }
        { float mn = fmaxf(M0, m0); S0 = S0*__expf(M0-mn) + s0*__expf(m0-mn); M0 = mn; }
        { float mn = fmaxf(M1, m1); S1 = S1*__expf(M1-mn) + s1*__expf(m1-mn); M1 = mn; }
    }

    if (tig == 0) {
        g_lse[r0 + rowA]     = M0 + __logf(S0);
        g_lse[r0 + rowA + 8] = M1 + __logf(S1);
    }
}

// ---------------- kernel 4: label-logit GEMM (N=128 padded labels) ----------------
__global__ __launch_bounds__(256, 1) void k_lab() {
    extern __shared__ __nv_bfloat16 sm[];
    __nv_bfloat16* As = sm;
    __nv_bfloat16* Ws = sm + 128*A_STR;
    const int tid = threadIdx.x;
    const int w = tid >> 5, lane = tid & 31, g = lane >> 2, tig = lane & 3;
    const int mc = blockIdx.x, b = blockIdx.y;
    const int t0 = mc * 128;
    const __nv_bfloat16* Wsrc = g_Wlab + (size_t)b*128*Hz;

    for (int e = tid; e < 128*64; e += 256) {
        int row = e >> 6, c = e & 63;
        int t = t0 + row; if (t > Tz-1) t = Tz-1;   // clamp (guarded on write)
        *reinterpret_cast<uint4*>(As + row*A_STR + c*8) =
            *reinterpret_cast<const uint4*>(g_Abf + (size_t)(b*Tz + t)*Hz + c*8);
    }

    uint2 rg[8];
    #pragma unroll
    for (int q = 0; q < 8; q++) {
        int e = tid + q*256; int row = e >> 4, c = e & 15;
        rg[q] = *reinterpret_cast<const uint2*>(Wsrc + (size_t)row*Hz + c*4);
    }
    #pragma unroll
    for (int q = 0; q < 8; q++) {
        int e = tid + q*256; int row = e >> 4, c = e & 15;
        *reinterpret_cast<uint2*>(Ws + row*W_STR + c*4) = rg[q];
    }
    __syncthreads();

    float acc[16][4];
    #pragma unroll
    for (int i = 0; i < 16; i++) { acc[i][0]=0.f; acc[i][1]=0.f; acc[i][2]=0.f; acc[i][3]=0.f; }

    #pragma unroll 1
    for (int kc = 0; kc < 8; kc++) {
        if (kc < 7) {
            #pragma unroll
            for (int q = 0; q < 8; q++) {
                int e = tid + q*256; int row = e >> 4, c = e & 15;
                rg[q] = *reinterpret_cast<const uint2*>(Wsrc + (size_t)row*Hz + (kc+1)*64 + c*4);
            }
        }
        const __nv_bfloat16* Wb = Ws + (kc & 1) * (128*W_STR);
        const int rowA = w*16 + g;
        #pragma unroll
        for (int ks = 0; ks < 4; ks++) {
            const int kk = kc*64 + ks*16;
            uint32_t a0 = *reinterpret_cast<const uint32_t*>(As + rowA*A_STR + kk + 2*tig);
            uint32_t a1 = *reinterpret_cast<const uint32_t*>(As + (rowA+8)*A_STR + kk + 2*tig);
            uint32_t a2 = *reinterpret_cast<const uint32_t*>(As + rowA*A_STR + kk + 8 + 2*tig);
            uint32_t a3 = *reinterpret_cast<const uint32_t*>(As + (rowA+8)*A_STR + kk + 8 + 2*tig);
            #pragma unroll
            for (int nt = 0; nt < 16; nt++) {
                uint32_t b0 = *reinterpret_cast<const uint32_t*>(Wb + (nt*8+g)*W_STR + ks*16 + 2*tig);
                uint32_t b1 = *reinterpret_cast<const uint32_t*>(Wb + (nt*8+g)*W_STR + ks*16 + 8 + 2*tig);
                mma16816(acc[nt], a0, a1, a2, a3, b0, b1);
            }
        }
        __syncthreads();
        if (kc < 7) {
            __nv_bfloat16* Wd = Ws + ((kc+1) & 1) * (128*W_STR);
            #pragma unroll
            for (int q = 0; q < 8; q++) {
                int e = tid + q*256; int row = e >> 4, c = e & 15;
                *reinterpret_cast<uint2*>(Wd + row*W_STR + c*4) = rg[q];
            }
            __syncthreads();
        }
    }

    // Epilogue: write lp = logit + bias - lse for cols < 101, rows < T
    const int rowA = w*16 + g;
    int ta = t0 + rowA, tb = ta + 8;
    float lseA = (ta < Tz) ? g_lse[b*Tz + ta] : 0.f;
    float lseB = (tb < Tz) ? g_lse[b*Tz + tb] : 0.f;
    #pragma unroll
    for (int nt = 0; nt < 16; nt++) {
        int c0 = nt*8 + 2*tig, c1 = c0 + 1;
        float bb0 = g_blab[b*128 + c0], bb1 = g_blab[b*128 + c1];
        if (ta < Tz) {
            if (c0 < NLAB) g_lab[(size_t)(b*Tz+ta)*NLAB + c0] = acc[nt][0] + bb0 - lseA;
            if (c1 < NLAB) g_lab[(size_t)(b*Tz+ta)*NLAB + c1] = acc[nt][1] + bb1 - lseA;
        }
        if (tb < Tz) {
            if (c0 < NLAB) g_lab[(size_t)(b*Tz+tb)*NLAB + c0] = acc[nt][2] + bb0 - lseB;
            if (c1 < NLAB) g_lab[(size_t)(b*Tz+tb)*NLAB + c1] = acc[nt][3] + bb1 - lseB;
        }
    }
}

// ---------------- kernel 5: CTC forward DP ----------------
__global__ __launch_bounds__(256) void k_dp(const int* __restrict__ ys,
                                            const int* __restrict__ elens,
                                            const int* __restrict__ ylens) {
    __shared__ float abuf[2][224];
    const int b = blockIdx.x;
    const int s = threadIdx.x;
    const int elen = elens[b];
    const int ylen = ylens[b];
    const bool active = (s < Sz);
    const bool valid = (s < 2*ylen + 1);
    const int j = (s & 1) ? ((s >> 1) + 1) : 0;
    bool skip = false;
    if ((s & 1) && s >= 3 && s < Sz) {
        skip = (ys[b*Lz + (s >> 1)] != ys[b*Lz + (s >> 1) - 1]);
    }
    const float* lab = g_lab + (size_t)b*Tz*NLAB;

    // t = 0 init
    if (active) {
        float a = (s < 2) ? lab[j] : NEGINF;
        if (!valid) a = NEGINF;
        abuf[0][s] = a;
    }
    float lp_cur = active ? lab[(size_t)1*NLAB + j] : 0.f;
    float lp_nxt = (active && 2 < elen) ? lab[(size_t)2*NLAB + j] : 0.f;
    __syncthreads();

    int pp = 0;
    for (int t = 1; t < elen; t++) {
        float nv = NEGINF;
        if (active && valid) {
            float x0 = abuf[pp][s];
            float x1 = (s >= 1) ? abuf[pp][s-1] : NEGINF;
            float x2 = skip ? abuf[pp][s-2] : NEGINF;
            float m = fmaxf(x0, fmaxf(x1, x2));
            float sum = __expf(x0-m) + __expf(x1-m) + __expf(x2-m);
            nv = m + __logf(sum) + lp_cur;
        }
        lp_cur = lp_nxt;
        lp_nxt = (active && (t + 2) < elen) ? lab[(size_t)(t+2)*NLAB + j] : 0.f;
        if (active) abuf[pp ^ 1][s] = nv;
        __syncthreads();
        pp ^= 1;
    }

    if (s == 0) {
        float last = abuf[pp][2*ylen];
        float prev = abuf[pp][2*ylen - 1];
        float m = fmaxf(last, prev);
        float loss = -(m + __logf(__expf(last-m) + __expf(prev-m)));
        g_lossb[b] = (loss < -0.5f*NEGINF) ? loss : 0.f;
    }
}

// ---------------- kernel 6: deterministic finalize ----------------
__global__ void k_final(float* __restrict__ out) {
    if (threadIdx.x == 0 && blockIdx.x == 0) {
        float s = 0.f;
        for (int b = 0; b < Bz; b++) s += g_lossb[b];
        out[0] = s / (float)Bz;
    }
}

// ---------------- entry ----------------
extern "C" void kernel_launch(void* const* d_in, const int* in_sizes, int n_in,
                              void* d_out, int out_size) {
    const float* eouts = (const float*)d_in[0];
    const float* W     = (const float*)d_in[1];
    const float* bias  = (const float*)d_in[2];
    const int*   ys    = (const int*)d_in[3];
    const int*   elens = (const int*)d_in[4];
    const int*   ylens = (const int*)d_in[5];
    float* out = (float*)d_out;

    cudaFuncSetAttribute(k_lse, cudaFuncAttributeMaxDynamicSharedMemorySize, SMEM_BYTES);
    cudaFuncSetAttribute(k_lab, cudaFuncAttributeMaxDynamicSharedMemorySize, SMEM_BYTES);

    k_convert<<<2048, 256>>>(eouts, W);
    k_gather<<<Bz*128, 64>>>(bias, ys);
    k_lse<<<BTz/128, 256, SMEM_BYTES>>>(bias);
    k_lab<<<dim3((Tz + 127)/128, Bz), 256, SMEM_BYTES>>>();
    k_dp<<<Bz, 256>>>(ys, elens, ylens);
    k_final<<<1, 32>>>(out);
}